// round 7
// baseline (speedup 1.0000x reference)
#include <cuda_runtime.h>
#include <cstdint>
#include <cmath>

// ---------------- problem constants ----------------
#define Nn 8192
#define Dd 64
#define Pp 32
#define Mm 50
#define Hh 512
#define KX 96              // D + P  (s column folded separately)

// ---------------- tiling ----------------
#define Rr 64              // rows per CTA
#define NBLOCKS (Nn / Rr)  // 128
#define THREADS 256        // 8 warps
#define CHUNK 64           // H columns per chunk
#define NCHUNK (Hh / CHUNK)
#define KQ1 (KX / 4)       // 24 k-quads in GEMM1
#define KQ2 (CHUNK / 4)    // 16 k-quads in GEMM2

// padded strides (floats); all ≡ 4 (mod 32) and ≡ 0 (mod 4)
#define XS 100             // sX row stride
#define HS 68              // sH row stride
#define W1S 100            // W1t image: [64 c][100] per chunk
#define W1IMG (CHUNK * W1S)      // 6400 floats
#define W2S 516            // W2t: [64 d][516]
#define W2SZ (Dd * W2S)          // 33024 floats

// smem layout (float offsets)
#define OFF_W2T 0
#define OFF_W1  (OFF_W2T + W2SZ)
#define OFF_X   (OFF_W1 + 2 * W1IMG)
#define OFF_H   (OFF_X + Rr * XS)
#define OFF_B1  (OFF_H + Rr * HS)
#define OFF_W0  (OFF_B1 + Hh)
#define SMEM_FLOATS (OFF_W0 + Hh)
#define SMEM_BYTES (SMEM_FLOATS * 4)      // 230400

typedef unsigned long long u64;

__device__ float gW1t[NCHUNK * W1IMG];    // [chunk][c][k]
__device__ float gW2t[W2SZ];              // [d][k]

// ---------------- helpers ----------------
__device__ __forceinline__ void fma2(u64& acc, u64 a, u64 b) {
    asm("fma.rn.f32x2 %0, %1, %2, %0;" : "+l"(acc) : "l"(a), "l"(b));
}
__device__ __forceinline__ float2 upk(u64 v) {
    float2 r; asm("mov.b64 {%0,%1}, %2;" : "=f"(r.x), "=f"(r.y) : "l"(v)); return r;
}
__device__ __forceinline__ float fast_tanh(float x) {
    float y; asm("tanh.approx.f32 %0, %1;" : "=f"(y) : "f"(x)); return y;
}
__device__ __forceinline__ void cp16(uint32_t dst, const float* src) {
    asm volatile("cp.async.cg.shared.global [%0], [%1], 16;" :: "r"(dst), "l"(src));
}
#define CP_COMMIT() asm volatile("cp.async.commit_group;")
#define CP_WAIT1()  asm volatile("cp.async.wait_group 1;")

// ---------------- setup: transpose weights ----------------
__global__ void transpose_weights(const float* __restrict__ W1,
                                  const float* __restrict__ W2) {
    int tid = blockIdx.x * blockDim.x + threadIdx.x;
    int stride = gridDim.x * blockDim.x;
    for (int i = tid; i < NCHUNK * CHUNK * KX; i += stride) {
        int ch = i / (CHUNK * KX);
        int r  = i % (CHUNK * KX);
        int c  = r / KX;
        int k  = r % KX;
        gW1t[ch * W1IMG + c * W1S + k] = W1[(size_t)(k + 1) * Hh + ch * CHUNK + c];
    }
    for (int i = tid; i < Dd * Hh; i += stride) {
        int d = i / Hh;
        int k = i % Hh;
        gW2t[d * W2S + k] = W2[(size_t)k * Dd + d];
    }
}

// ---------------- main persistent rollout kernel ----------------
__global__ void __launch_bounds__(THREADS, 1) sim_rollout_kernel(
    const float* __restrict__ X0, const float* __restrict__ V0,
    const float* __restrict__ Y,  const float* __restrict__ theta,
    const float* __restrict__ W1, const float* __restrict__ b1,
    const float* __restrict__ W2, const float* __restrict__ b2,
    const float* __restrict__ noise, const int* __restrict__ obs_index,
    float* __restrict__ out)
{
    extern __shared__ float sm[];
    float* sW2t = sm + OFF_W2T;
    float* sW1  = sm + OFF_W1;
    float* sX   = sm + OFF_X;
    float* sH   = sm + OFF_H;
    float* sB1  = sm + OFF_B1;
    float* sW0  = sm + OFF_W0;

    const int tid = threadIdx.x;
    const int w   = tid >> 5;
    const int l   = tid & 31;
    const int row0 = blockIdx.x * Rr;

    // warp owns 8 consecutive rows; thread: 2 rows x 8 cols (cols strided 8)
    const int rgrp = l >> 3;             // 0..3
    const int cgrp = l & 7;              // 0..7
    const int r0   = w * 8 + rgrp * 2;   // rows r0, r0+1
    // cols/d: cgrp + 8*j, j = 0..7

    const float dt   = 1.0f / (float)Mm;
    const float sqdt = sqrtf(dt);
    const int obs = *obs_index;

    // ---- one-time staging ----
    for (int idx = tid; idx < W2SZ / 4; idx += THREADS)
        ((float4*)sW2t)[idx] = ((const float4*)gW2t)[idx];
    for (int idx = tid; idx < Rr * Dd; idx += THREADS) {
        int r = idx >> 6, d = idx & 63;
        sX[r * XS + d] = X0[(size_t)(row0 + r) * Dd + d];
    }
    for (int idx = tid; idx < Rr * Pp; idx += THREADS) {
        int r = idx >> 5, p = idx & 31;
        sX[r * XS + 64 + p] = Y[(size_t)(row0 + r) * Pp + obs * Pp + p];
    }
    for (int idx = tid; idx < Hh; idx += THREADS) {
        sB1[idx] = b1[idx];
        sW0[idx] = W1[idx];              // W1 row 0 (s-column weights)
    }

    float thc[8], b2c[8];
    #pragma unroll
    for (int j = 0; j < 8; j++) {
        thc[j] = theta[cgrp + 8 * j];
        b2c[j] = b2[cgrp + 8 * j];
    }
    float vreg[2];
    #pragma unroll
    for (int i = 0; i < 2; i++) vreg[i] = V0[row0 + r0 + i];

    // prime cp.async: chunk 0 -> buffer 0
    const uint32_t w1sa = (uint32_t)__cvta_generic_to_shared(sW1);
    for (int idx = tid; idx < W1IMG / 4; idx += THREADS)
        cp16(w1sa + idx * 16, gW1t + idx * 4);
    CP_COMMIT();

    const float* aP1 = sX + r0 * XS;
    const float* aP2 = sH + r0 * HS;

    // ---- 50-step rollout ----
    for (int m = 0; m < Mm; ++m) {
        const float s = (float)m * dt;

        float nz[2][8];
        const float* nb = noise + ((size_t)m * Nn + row0) * Dd;
        #pragma unroll
        for (int i = 0; i < 2; i++)
            #pragma unroll
            for (int j = 0; j < 8; j++)
                nz[i][j] = nb[(size_t)(r0 + i) * Dd + cgrp + 8 * j];

        u64 zacc[2][8];
        #pragma unroll
        for (int i = 0; i < 2; i++)
            #pragma unroll
            for (int j = 0; j < 8; j++) zacc[i][j] = 0ull;

        for (int ch = 0; ch < NCHUNK; ++ch) {
            // prefetch next chunk's W1 image into the other buffer
            {
                int nxt = (ch + 1) & 7;
                uint32_t dst = w1sa + (uint32_t)(((ch + 1) & 1) * W1IMG) * 4u;
                const float* src = gW1t + nxt * W1IMG;
                for (int idx = tid; idx < W1IMG / 4; idx += THREADS)
                    cp16(dst + idx * 16, src + idx * 4);
                CP_COMMIT();
            }
            CP_WAIT1();
            __syncthreads();

            const float* w1b = sW1 + (ch & 1) * W1IMG + cgrp * W1S;

            float hb[8];
            #pragma unroll
            for (int j = 0; j < 8; j++) {
                int c = ch * CHUNK + cgrp + 8 * j;
                hb[j] = s * sW0[c] + sB1[c];
            }

            // ---- GEMM1, software-pipelined one quad ahead ----
            u64 acc[2][8];
            #pragma unroll
            for (int i = 0; i < 2; i++)
                #pragma unroll
                for (int j = 0; j < 8; j++) acc[i][j] = 0ull;

            {
                ulonglong2 A[2][2], B[2][8];
                #pragma unroll
                for (int i = 0; i < 2; i++)
                    A[0][i] = *(const ulonglong2*)(aP1 + i * XS);
                #pragma unroll
                for (int j = 0; j < 8; j++)
                    B[0][j] = *(const ulonglong2*)(w1b + j * 8 * W1S);

                #pragma unroll
                for (int q = 0; q < KQ1; ++q) {
                    const int cur = q & 1, nxt = cur ^ 1;
                    if (q + 1 < KQ1) {
                        #pragma unroll
                        for (int i = 0; i < 2; i++)
                            A[nxt][i] = *(const ulonglong2*)(aP1 + i * XS + (q + 1) * 4);
                        #pragma unroll
                        for (int j = 0; j < 8; j++)
                            B[nxt][j] = *(const ulonglong2*)(w1b + j * 8 * W1S + (q + 1) * 4);
                    }
                    #pragma unroll
                    for (int i = 0; i < 2; i++)
                        #pragma unroll
                        for (int j = 0; j < 8; j++) {
                            fma2(acc[i][j], A[cur][i].x, B[cur][j].x);
                            fma2(acc[i][j], A[cur][i].y, B[cur][j].y);
                        }
                }
            }

            // bias + tanh -> sH (warp-local rows); banks all distinct -> 1 wf/STS
            #pragma unroll
            for (int i = 0; i < 2; i++)
                #pragma unroll
                for (int j = 0; j < 8; j++) {
                    float2 t = upk(acc[i][j]);
                    sH[(r0 + i) * HS + cgrp + 8 * j] = fast_tanh(t.x + t.y + hb[j]);
                }
            __syncwarp();

            // ---- GEMM2, software-pipelined one quad ahead ----
            {
                const float* w2b = sW2t + cgrp * W2S + ch * CHUNK;
                ulonglong2 A[2][2], B[2][8];
                #pragma unroll
                for (int i = 0; i < 2; i++)
                    A[0][i] = *(const ulonglong2*)(aP2 + i * HS);
                #pragma unroll
                for (int j = 0; j < 8; j++)
                    B[0][j] = *(const ulonglong2*)(w2b + j * 8 * W2S);

                #pragma unroll
                for (int q = 0; q < KQ2; ++q) {
                    const int cur = q & 1, nxt = cur ^ 1;
                    if (q + 1 < KQ2) {
                        #pragma unroll
                        for (int i = 0; i < 2; i++)
                            A[nxt][i] = *(const ulonglong2*)(aP2 + i * HS + (q + 1) * 4);
                        #pragma unroll
                        for (int j = 0; j < 8; j++)
                            B[nxt][j] = *(const ulonglong2*)(w2b + j * 8 * W2S + (q + 1) * 4);
                    }
                    #pragma unroll
                    for (int i = 0; i < 2; i++)
                        #pragma unroll
                        for (int j = 0; j < 8; j++) {
                            fma2(zacc[i][j], A[cur][i].x, B[cur][j].x);
                            fma2(zacc[i][j], A[cur][i].y, B[cur][j].y);
                        }
                }
            }
        }

        // ---- epilogue: V and X updates (warp-local) ----
        #pragma unroll
        for (int i = 0; i < 2; i++) {
            float vpart = 0.0f;
            #pragma unroll
            for (int j = 0; j < 8; j++) {
                float2 t = upk(zacc[i][j]);
                float z  = t.x + t.y + b2c[j];
                float wm = sqdt * nz[i][j];
                vpart += z * wm - 0.5f * dt * z * z;
                float* xp = &sX[(r0 + i) * XS + cgrp + 8 * j];
                float xo = *xp;
                *xp = xo + dt * (thc[j] - xo - z) + wm;
            }
            // row r0+i is owned by the 8 contiguous lanes rgrp*8 .. rgrp*8+7
            vpart += __shfl_down_sync(0xffffffffu, vpart, 4, 8);
            vpart += __shfl_down_sync(0xffffffffu, vpart, 2, 8);
            vpart += __shfl_down_sync(0xffffffffu, vpart, 1, 8);
            vreg[i] += vpart;
        }
        __syncwarp();
    }

    __syncthreads();
    // ---- output: X then V ----
    for (int idx = tid; idx < Rr * Dd; idx += THREADS) {
        int r = idx >> 6, d = idx & 63;
        out[(size_t)(row0 + r) * Dd + d] = sX[r * XS + d];
    }
    if (cgrp == 0) {
        #pragma unroll
        for (int i = 0; i < 2; i++)
            out[(size_t)Nn * Dd + row0 + r0 + i] = vreg[i];
    }
}

extern "C" void kernel_launch(void* const* d_in, const int* in_sizes, int n_in,
                              void* d_out, int out_size)
{
    (void)in_sizes; (void)n_in; (void)out_size;
    cudaFuncSetAttribute(sim_rollout_kernel,
                         cudaFuncAttributeMaxDynamicSharedMemorySize, SMEM_BYTES);

    transpose_weights<<<64, 256>>>((const float*)d_in[4], (const float*)d_in[6]);
    sim_rollout_kernel<<<NBLOCKS, THREADS, SMEM_BYTES>>>(
        (const float*)d_in[0], (const float*)d_in[1], (const float*)d_in[2],
        (const float*)d_in[3], (const float*)d_in[4], (const float*)d_in[5],
        (const float*)d_in[6], (const float*)d_in[7], (const float*)d_in[8],
        (const int*)d_in[9],   (float*)d_out);
}

// round 10
// speedup vs baseline: 4.2787x; 4.2787x over previous
#include <cuda_runtime.h>
#include <cuda_bf16.h>
#include <cstdint>
#include <cmath>

// ---------------- problem constants ----------------
#define Nn 8192
#define Mm 50

#define CTA_ROWS 64
#define GRID (Nn / CTA_ROWS)   // 128
#define THREADS 128            // 4 warps, each owns 16 rows

// weight fragment image: per chunk, uint2 entries
//   W1: [h(2)][ks(6)][nt(8)][lane(32)]  -> 3072 uint2
//   W2: [h(2)][ks(4)][nt(8)][lane(32)]  -> 2048 uint2, at offset 3072
#define WCH_U2 5120
#define W2_OFF 3072
#define WCH_B  (WCH_U2 * 8)    // 40960 bytes per chunk

// smem layout (bytes)
#define NZ_STRIDE 68                      // floats; 272 B ≡ 0 (mod 16): cp.async-safe
#define NZ_BUF (64 * NZ_STRIDE * 4)       // 17408
#define SM_W   0                          // 2 * 40960 = 81920
#define SM_NZ  81920                      // 2 * 17408 = 34816
#define SM_W0  (SM_NZ + 2 * NZ_BUF)       // 116736
#define SM_B1  (SM_W0 + 2048)
#define SM_B2  (SM_B1 + 2048)
#define SM_TH  (SM_B2 + 256)
#define SMEM_BYTES (SM_TH + 256)          // 121344

__device__ __align__(16) uint2 gWf[8][WCH_U2];

// ---------------- helpers ----------------
__device__ __forceinline__ float ftanh(float x) {
    float y; asm("tanh.approx.f32 %0, %1;" : "=f"(y) : "f"(x)); return y;
}
__device__ __forceinline__ void cp16(uint32_t dst, const void* src) {
    asm volatile("cp.async.cg.shared.global [%0], [%1], 16;" :: "r"(dst), "l"(src));
}
#define CP_COMMIT() asm volatile("cp.async.commit_group;" ::: "memory")
#define CP_WAIT0()  asm volatile("cp.async.wait_group 0;" ::: "memory")

// split two fp32 (xe = even-k, xo = odd-k) into bf16x2 hi and lo words, even in low half
__device__ __forceinline__ void split_pair(float xe, float xo, uint32_t& whi, uint32_t& wlo) {
    uint32_t h;
    asm("cvt.rn.bf16x2.f32 %0, %1, %2;" : "=r"(h) : "f"(xo), "f"(xe));
    float fe = __uint_as_float(h << 16);
    float fo = __uint_as_float(h & 0xFFFF0000u);
    uint32_t lw;
    asm("cvt.rn.bf16x2.f32 %0, %1, %2;" : "=r"(lw) : "f"(xo - fo), "f"(xe - fe));
    whi = h; wlo = lw;
}

__device__ __forceinline__ void mma16816(float d[4],
    uint32_t a0, uint32_t a1, uint32_t a2, uint32_t a3, uint2 b) {
    asm volatile(
        "mma.sync.aligned.m16n8k16.row.col.f32.bf16.bf16.f32 "
        "{%0,%1,%2,%3}, {%4,%5,%6,%7}, {%8,%9}, {%0,%1,%2,%3};"
        : "+f"(d[0]), "+f"(d[1]), "+f"(d[2]), "+f"(d[3])
        : "r"(a0), "r"(a1), "r"(a2), "r"(a3), "r"(b.x), "r"(b.y));
}

// ---------------- setup: prepack weights into B-fragment order, bf16 hi/lo ----
__global__ void build_frags(const float* __restrict__ W1, const float* __restrict__ W2) {
    int tid = blockIdx.x * blockDim.x + threadIdx.x;
    int stride = gridDim.x * blockDim.x;

    // W1 frags: 8ch x 2h x 6ks x 8nt x 32l = 24576 uint2
    for (int i = tid; i < 24576; i += stride) {
        int l  = i & 31;
        int nt = (i >> 5) & 7;
        int r8 = i >> 8;
        int ks = r8 % 6;
        int h  = (r8 / 6) & 1;
        int ch = i / 3072;
        int n  = ch * 64 + nt * 8 + (l >> 2);
        int k0 = ks * 16 + (l & 3) * 2;
        float v[4] = { W1[(size_t)(1 + k0) * 512 + n], W1[(size_t)(2 + k0) * 512 + n],
                       W1[(size_t)(9 + k0) * 512 + n], W1[(size_t)(10 + k0) * 512 + n] };
        uint32_t p[2];
        #pragma unroll
        for (int q = 0; q < 2; q++) {
            float a = v[2*q], bq = v[2*q + 1];
            if (h) {
                a  -= __bfloat162float(__float2bfloat16(a));
                bq -= __bfloat162float(__float2bfloat16(bq));
            }
            p[q] = (uint32_t)__bfloat16_as_ushort(__float2bfloat16(a))
                 | ((uint32_t)__bfloat16_as_ushort(__float2bfloat16(bq)) << 16);
        }
        gWf[ch][((h * 6 + ks) * 8 + nt) * 32 + l] = make_uint2(p[0], p[1]);
    }

    // W2 frags: 8ch x 2h x 4ks x 8nt x 32l = 16384 uint2
    for (int i = tid; i < 16384; i += stride) {
        int l  = i & 31;
        int nt = (i >> 5) & 7;
        int r8 = i >> 8;
        int ks = r8 % 4;
        int h  = (r8 / 4) & 1;
        int ch = i / 2048;
        int n  = nt * 8 + (l >> 2);
        int k0 = ch * 64 + ks * 16 + (l & 3) * 2;
        float v[4] = { W2[(size_t)k0 * 64 + n],       W2[(size_t)(k0 + 1) * 64 + n],
                       W2[(size_t)(k0 + 8) * 64 + n], W2[(size_t)(k0 + 9) * 64 + n] };
        uint32_t p[2];
        #pragma unroll
        for (int q = 0; q < 2; q++) {
            float a = v[2*q], bq = v[2*q + 1];
            if (h) {
                a  -= __bfloat162float(__float2bfloat16(a));
                bq -= __bfloat162float(__float2bfloat16(bq));
            }
            p[q] = (uint32_t)__bfloat16_as_ushort(__float2bfloat16(a))
                 | ((uint32_t)__bfloat16_as_ushort(__float2bfloat16(bq)) << 16);
        }
        gWf[ch][W2_OFF + ((h * 4 + ks) * 8 + nt) * 32 + l] = make_uint2(p[0], p[1]);
    }
}

// ---------------- main rollout: warp-level bf16 MMA, 3-term split ----------------
__global__ void __launch_bounds__(THREADS, 1) rollout_mma(
    const float* __restrict__ X0, const float* __restrict__ V0,
    const float* __restrict__ Y,  const float* __restrict__ theta,
    const float* __restrict__ W1, const float* __restrict__ b1,
    const float* __restrict__ W2, const float* __restrict__ b2,
    const float* __restrict__ noise, const int* __restrict__ obs_index,
    float* __restrict__ out)
{
    extern __shared__ __align__(16) unsigned char smem[];
    uint2* sW  = (uint2*)(smem + SM_W);
    float* sNZ = (float*)(smem + SM_NZ);
    float* sW0 = (float*)(smem + SM_W0);
    float* sB1 = (float*)(smem + SM_B1);
    float* sB2 = (float*)(smem + SM_B2);
    float* sTH = (float*)(smem + SM_TH);
    const uint32_t sb = (uint32_t)__cvta_generic_to_shared(smem);

    const int tid = threadIdx.x;
    const int w = tid >> 5, l = tid & 31;
    const int g = l >> 2, c = l & 3;
    const int row0 = blockIdx.x * CTA_ROWS;
    const int rA = row0 + w * 16 + g;       // fragment row (groupID)
    const int rB = rA + 8;                  // fragment row (groupID+8)

    const float dt = 1.0f / (float)Mm;
    const float sqdt = sqrtf(dt);
    const int obs = *obs_index;

    for (int i = tid; i < 512; i += THREADS) { sW0[i] = W1[i]; sB1[i] = b1[i]; }
    if (tid < 64) { sB2[tid] = b2[tid]; sTH[tid] = theta[tid]; }

    // X fp32 state, fragment-distributed: X[j] = {(rA,2c+8j),(rA,+1),(rB,2c+8j),(rB,+1)}
    float X[8][4];
    #pragma unroll
    for (int j = 0; j < 8; j++) {
        int col = c * 2 + 8 * j;
        float2 va = *(const float2*)(X0 + (size_t)rA * 64 + col);
        float2 vb = *(const float2*)(X0 + (size_t)rB * 64 + col);
        X[j][0] = va.x; X[j][1] = va.y; X[j][2] = vb.x; X[j][3] = vb.y;
    }

    // Y A-fragments (static across steps): GEMM1 k-steps 4,5
    uint32_t Yhi[2][4], Ylo[2][4];
    #pragma unroll
    for (int ks = 0; ks < 2; ks++)
        #pragma unroll
        for (int r = 0; r < 2; r++) {
            int yc = ks * 16 + c * 2 + r * 8;
            float2 ya = *(const float2*)(Y + (size_t)rA * 32 + (size_t)obs * 32 + yc);
            float2 yb = *(const float2*)(Y + (size_t)rB * 32 + (size_t)obs * 32 + yc);
            split_pair(ya.x, ya.y, Yhi[ks][2*r],     Ylo[ks][2*r]);
            split_pair(yb.x, yb.y, Yhi[ks][2*r + 1], Ylo[ks][2*r + 1]);
        }

    // X A-fragments (rebuilt per step)
    uint32_t Xhi[4][4], Xlo[4][4];
    auto build_xfrags = [&]() {
        #pragma unroll
        for (int ks = 0; ks < 4; ks++) {
            split_pair(X[2*ks][0],     X[2*ks][1],     Xhi[ks][0], Xlo[ks][0]);
            split_pair(X[2*ks][2],     X[2*ks][3],     Xhi[ks][1], Xlo[ks][1]);
            split_pair(X[2*ks + 1][0], X[2*ks + 1][1], Xhi[ks][2], Xlo[ks][2]);
            split_pair(X[2*ks + 1][2], X[2*ks + 1][3], Xhi[ks][3], Xlo[ks][3]);
        }
    };
    build_xfrags();

    float vA = 0.0f, vB = 0.0f;

    // prime: chunk 0 weights + step 0 noise
    {
        const uint2* src = gWf[0];
        for (int i = tid; i < WCH_U2 / 2; i += THREADS)
            cp16(sb + SM_W + i * 16, src + i * 2);
        const float* nb = noise + (size_t)row0 * 64;
        for (int i = tid; i < 1024; i += THREADS) {
            int r = i >> 4, jj = i & 15;
            cp16(sb + SM_NZ + r * (NZ_STRIDE * 4) + jj * 16, nb + (size_t)r * 64 + jj * 4);
        }
        CP_COMMIT();
    }

    for (int m = 0; m < Mm; m++) {
        const float s = (float)m * dt;
        float D2[8][4];
        #pragma unroll
        for (int nt = 0; nt < 8; nt++)
            #pragma unroll
            for (int i = 0; i < 4; i++) D2[nt][i] = 0.0f;

        for (int ch = 0; ch < 8; ch++) {
            const int gc = m * 8 + ch;
            CP_WAIT0();
            __syncthreads();              // weights(gc) visible; all warps done with gc-1

            // prefetch next chunk weights (issued AFTER barrier: no buffer race)
            {
                const uint2* src = gWf[(ch + 1) & 7];
                uint32_t dst = sb + SM_W + (((gc + 1) & 1) ? (uint32_t)WCH_B : 0u);
                for (int i = tid; i < WCH_U2 / 2; i += THREADS)
                    cp16(dst + i * 16, src + i * 2);
                CP_COMMIT();
            }
            if (ch == 4 && m + 1 < Mm) {   // stage next step's noise mid-step
                const float* nb = noise + ((size_t)(m + 1) * Nn + (size_t)row0) * 64;
                uint32_t nzd = sb + SM_NZ + (((m + 1) & 1) ? (uint32_t)NZ_BUF : 0u);
                for (int i = tid; i < 1024; i += THREADS) {
                    int r = i >> 4, jj = i & 15;
                    cp16(nzd + r * (NZ_STRIDE * 4) + jj * 16, nb + (size_t)r * 64 + jj * 4);
                }
                CP_COMMIT();
            }

            const uint2* wb = sW + (gc & 1) * WCH_U2;

            // ---- GEMM1: C1[16x64] = [X|Y] @ W1chunk, 3-term split ----
            float C1[8][4];
            #pragma unroll
            for (int nt = 0; nt < 8; nt++)
                #pragma unroll
                for (int i = 0; i < 4; i++) C1[nt][i] = 0.0f;

            #pragma unroll
            for (int ks = 0; ks < 6; ks++) {
                uint32_t AH[4], AL[4];
                #pragma unroll
                for (int q = 0; q < 4; q++) {
                    AH[q] = (ks < 4) ? Xhi[ks & 3][q] : Yhi[ks & 1][q];
                    AL[q] = (ks < 4) ? Xlo[ks & 3][q] : Ylo[ks & 1][q];
                }
                uint2 bh = wb[(ks * 8) * 32 + l];
                uint2 bl = wb[((6 + ks) * 8) * 32 + l];
                #pragma unroll
                for (int nt = 0; nt < 8; nt++) {
                    uint2 bh2, bl2;
                    if (nt < 7) {
                        bh2 = wb[(ks * 8 + nt + 1) * 32 + l];
                        bl2 = wb[((6 + ks) * 8 + nt + 1) * 32 + l];
                    }
                    mma16816(C1[nt], AH[0], AH[1], AH[2], AH[3], bh);
                    mma16816(C1[nt], AL[0], AL[1], AL[2], AL[3], bh);
                    mma16816(C1[nt], AH[0], AH[1], AH[2], AH[3], bl);
                    bh = bh2; bl = bl2;
                }
            }

            // ---- bias + tanh + split -> GEMM2 (C1 frags become A frags) ----
            const int cbase = ch * 64;
            #pragma unroll
            for (int ks2 = 0; ks2 < 4; ks2++) {
                int col0 = cbase + ks2 * 16 + c * 2;
                float2 w0a = *(const float2*)&sW0[col0];
                float2 b1a = *(const float2*)&sB1[col0];
                float2 w0b = *(const float2*)&sW0[col0 + 8];
                float2 b1b = *(const float2*)&sB1[col0 + 8];
                float hb0 = fmaf(s, w0a.x, b1a.x), hb1 = fmaf(s, w0a.y, b1a.y);
                float hb2 = fmaf(s, w0b.x, b1b.x), hb3 = fmaf(s, w0b.y, b1b.y);
                float h00 = ftanh(C1[2*ks2][0] + hb0);
                float h01 = ftanh(C1[2*ks2][1] + hb1);
                float h02 = ftanh(C1[2*ks2][2] + hb0);
                float h03 = ftanh(C1[2*ks2][3] + hb1);
                float h10 = ftanh(C1[2*ks2 + 1][0] + hb2);
                float h11 = ftanh(C1[2*ks2 + 1][1] + hb3);
                float h12 = ftanh(C1[2*ks2 + 1][2] + hb2);
                float h13 = ftanh(C1[2*ks2 + 1][3] + hb3);
                uint32_t ah0, ah1, ah2, ah3, al0, al1, al2, al3;
                split_pair(h00, h01, ah0, al0);
                split_pair(h02, h03, ah1, al1);
                split_pair(h10, h11, ah2, al2);
                split_pair(h12, h13, ah3, al3);

                uint2 bh = wb[W2_OFF + (ks2 * 8) * 32 + l];
                uint2 bl = wb[W2_OFF + ((4 + ks2) * 8) * 32 + l];
                #pragma unroll
                for (int nt = 0; nt < 8; nt++) {
                    uint2 bh2, bl2;
                    if (nt < 7) {
                        bh2 = wb[W2_OFF + (ks2 * 8 + nt + 1) * 32 + l];
                        bl2 = wb[W2_OFF + ((4 + ks2) * 8 + nt + 1) * 32 + l];
                    }
                    mma16816(D2[nt], ah0, ah1, ah2, ah3, bh);
                    mma16816(D2[nt], al0, al1, al2, al3, bh);
                    mma16816(D2[nt], ah0, ah1, ah2, ah3, bl);
                    bh = bh2; bl = bl2;
                }
            }
        }

        // ---- step epilogue: Z -> V, X update (all register/fragment local) ----
        const float* nzb = sNZ + (m & 1) * (NZ_BUF / 4) + (w * 16 + g) * NZ_STRIDE + c * 2;
        #pragma unroll
        for (int nt = 0; nt < 8; nt++) {
            int col = c * 2 + 8 * nt;
            float2 b2v = *(const float2*)&sB2[col];
            float2 thv = *(const float2*)&sTH[col];
            float2 na  = *(const float2*)(nzb + 8 * nt);
            float2 nb2 = *(const float2*)(nzb + 8 * NZ_STRIDE + 8 * nt);
            float z0 = D2[nt][0] + b2v.x, z1 = D2[nt][1] + b2v.y;
            float z2 = D2[nt][2] + b2v.x, z3 = D2[nt][3] + b2v.y;
            float wa0 = sqdt * na.x,  wa1 = sqdt * na.y;
            float wb0 = sqdt * nb2.x, wb1 = sqdt * nb2.y;
            vA += z0 * wa0 + z1 * wa1 - 0.5f * dt * (z0 * z0 + z1 * z1);
            vB += z2 * wb0 + z3 * wb1 - 0.5f * dt * (z2 * z2 + z3 * z3);
            X[nt][0] += dt * (thv.x - X[nt][0] - z0) + wa0;
            X[nt][1] += dt * (thv.y - X[nt][1] - z1) + wa1;
            X[nt][2] += dt * (thv.x - X[nt][2] - z2) + wb0;
            X[nt][3] += dt * (thv.y - X[nt][3] - z3) + wb1;
        }
        build_xfrags();
    }

    // ---- output ----
    #pragma unroll
    for (int nt = 0; nt < 8; nt++) {
        int col = c * 2 + 8 * nt;
        *(float2*)(out + (size_t)rA * 64 + col) = make_float2(X[nt][0], X[nt][1]);
        *(float2*)(out + (size_t)rB * 64 + col) = make_float2(X[nt][2], X[nt][3]);
    }
    vA += __shfl_down_sync(0xffffffffu, vA, 2, 4);
    vA += __shfl_down_sync(0xffffffffu, vA, 1, 4);
    vB += __shfl_down_sync(0xffffffffu, vB, 2, 4);
    vB += __shfl_down_sync(0xffffffffu, vB, 1, 4);
    if (c == 0) {
        out[(size_t)Nn * 64 + rA] = V0[rA] + vA;
        out[(size_t)Nn * 64 + rB] = V0[rB] + vB;
    }
}

extern "C" void kernel_launch(void* const* d_in, const int* in_sizes, int n_in,
                              void* d_out, int out_size)
{
    (void)in_sizes; (void)n_in; (void)out_size;
    cudaFuncSetAttribute(rollout_mma,
                         cudaFuncAttributeMaxDynamicSharedMemorySize, SMEM_BYTES);

    build_frags<<<64, 256>>>((const float*)d_in[4], (const float*)d_in[6]);
    rollout_mma<<<GRID, THREADS, SMEM_BYTES>>>(
        (const float*)d_in[0], (const float*)d_in[1], (const float*)d_in[2],
        (const float*)d_in[3], (const float*)d_in[4], (const float*)d_in[5],
        (const float*)d_in[6], (const float*)d_in[7], (const float*)d_in[8],
        (const int*)d_in[9],   (float*)d_out);
}